// round 1
// baseline (speedup 1.0000x reference)
#include <cuda_runtime.h>
#include <cuda_bf16.h>
#include <cstdint>
#include <cstddef>

// ---------------------------------------------------------------------------
// Problem constants
// ---------------------------------------------------------------------------
#define V_SZ   32000
#define E_DIM  256
#define H_SZ   1024
#define BATCH  8
#define SEQ    512
#define ROWS   (BATCH*SEQ)          // 4096
#define LOGITS ((size_t)ROWS*V_SZ)  // 131072000

// ---------------------------------------------------------------------------
// Device scratch (static allocation — no cudaMalloc allowed)
// ---------------------------------------------------------------------------
__device__ float g_a0[(size_t)ROWS * H_SZ];     // precomputed input term [t*8+b][h]
__device__ float g_outs[(size_t)ROWS * H_SZ];   // h1 per step, row r=b*512+t
__device__ float g_h0buf[2][H_SZ * BATCH];      // [k*8+b] layout
__device__ float g_h1buf[2][H_SZ * BATCH];
__device__ unsigned          g_barc = 0;
__device__ volatile unsigned g_barg = 0;

// ---------------------------------------------------------------------------
// Kernel 1: embedding gather + input GEMM
//   g_a0[(t*8+b)*H + j] = emb[x[b,t]] @ W_ih0[:,j] + b_ih0[j] + b_hh0[j]
//   M=4096 (r = t*8+b), K=256, N=1024.  64x64 tiles, BK=64.
// ---------------------------------------------------------------------------
__global__ void __launch_bounds__(256) k_embed_gemm(
    const int* __restrict__ x, const float* __restrict__ emb,
    const float* __restrict__ Wih0, const float* __restrict__ bih0,
    const float* __restrict__ bhh0)
{
    __shared__ float sA[64][68];
    __shared__ float sB[64][68];
    const int n0 = blockIdx.x * 64;
    const int m0 = blockIdx.y * 64;
    const int tid = threadIdx.x;
    const int ty = tid >> 4, tx = tid & 15;

    float acc[4][4];
#pragma unroll
    for (int i = 0; i < 4; i++)
#pragma unroll
        for (int j = 0; j < 4; j++) acc[i][j] = 0.f;

    for (int k0 = 0; k0 < E_DIM; k0 += 64) {
        // stage A: 64 rows x 64 k  (gathered embedding rows)
#pragma unroll
        for (int i = 0; i < 4; i++) {
            int r  = (tid >> 4) + i * 16;   // 0..63
            int c4 = tid & 15;              // 0..15
            int rg = m0 + r;
            int t  = rg >> 3, b = rg & 7;
            int tok = x[b * SEQ + t];
            float4 v = *(const float4*)(emb + (size_t)tok * E_DIM + k0 + c4 * 4);
            *(float4*)&sA[r][c4 * 4] = v;
        }
        // stage B: 64 k x 64 n
#pragma unroll
        for (int i = 0; i < 4; i++) {
            int kr = (tid >> 4) + i * 16;
            int c4 = tid & 15;
            float4 v = *(const float4*)(Wih0 + (size_t)(k0 + kr) * H_SZ + n0 + c4 * 4);
            *(float4*)&sB[kr][c4 * 4] = v;
        }
        __syncthreads();
#pragma unroll 8
        for (int k = 0; k < 64; k++) {
            float a[4], bb[4];
#pragma unroll
            for (int i = 0; i < 4; i++) a[i] = sA[ty * 4 + i][k];
#pragma unroll
            for (int j = 0; j < 4; j++) bb[j] = sB[k][tx * 4 + j];
#pragma unroll
            for (int i = 0; i < 4; i++)
#pragma unroll
                for (int j = 0; j < 4; j++) acc[i][j] += a[i] * bb[j];
        }
        __syncthreads();
    }
#pragma unroll
    for (int i = 0; i < 4; i++) {
        int r = m0 + ty * 4 + i;
#pragma unroll
        for (int j = 0; j < 4; j++) {
            int n = n0 + tx * 4 + j;
            g_a0[(size_t)r * H_SZ + n] = acc[i][j] + bih0[n] + bhh0[n];
        }
    }
}

// ---------------------------------------------------------------------------
// Kernel 2: persistent recurrence. 128 CTAs x 256 threads; each CTA owns an
// 8-column slice of W_hh0 / W_ih1 / W_hh1 in SMEM. Grid barrier via atomics.
// ---------------------------------------------------------------------------
#define NCTA 128

__device__ __forceinline__ void grid_barrier()
{
    __syncthreads();
    __threadfence();
    if (threadIdx.x == 0) {
        unsigned gen = g_barg;
        unsigned a = atomicAdd(&g_barc, 1u);
        if (a == NCTA - 1) {
            g_barc = 0;
            __threadfence();
            g_barg = gen + 1;
        } else {
            while (g_barg == gen) __nanosleep(64);
        }
    }
    __syncthreads();
}

// SMEM plan (floats): sw0[8192] sw1[8192] sw2[8192] sh0[8192] sh1[8192]
//                     sred[512] sb[8]   -> 41480 floats = 165,920 B
#define RNN_SMEM_FLOATS 41480
#define RNN_SMEM_BYTES  (RNN_SMEM_FLOATS * 4)

__global__ void __launch_bounds__(256, 1) k_rnn(
    const float* __restrict__ Whh0, const float* __restrict__ Wih1,
    const float* __restrict__ Whh1, const float* __restrict__ bih1,
    const float* __restrict__ bhh1)
{
    extern __shared__ float sm[];
    float* sw0  = sm;
    float* sw1  = sm + 8192;
    float* sw2  = sm + 16384;
    float* sh0  = sm + 24576;
    float* sh1  = sm + 32768;
    float* sred = sm + 40960;   // 512
    float* sb   = sm + 41472;   // 8

    const int tid  = threadIdx.x;
    const int j0   = blockIdx.x * 8;
    const int jl   = tid & 7;
    const int kg   = tid >> 3;       // 0..31
    const int lane = tid & 31;
    const int warp = tid >> 5;

    // load weight slices: sw[k*8+jl] = W[k][j0+jl]
    for (int idx = tid; idx < 8192; idx += 256) {
        int jj = idx & 7, k = idx >> 3;
        sw0[idx] = Whh0[(size_t)k * H_SZ + j0 + jj];
        sw1[idx] = Wih1[(size_t)k * H_SZ + j0 + jj];
        sw2[idx] = Whh1[(size_t)k * H_SZ + j0 + jj];
    }
    if (tid < 8) sb[tid] = bih1[j0 + tid] + bhh1[j0 + tid];

    // zero initial hidden state (buffer 0), each CTA zeroes its 64-float chunk
    if (tid < 64) {
        __stcg(&g_h0buf[0][blockIdx.x * 64 + tid], 0.f);
        __stcg(&g_h1buf[0][blockIdx.x * 64 + tid], 0.f);
    }
    grid_barrier();

    for (int t = 0; t < SEQ; t++) {
        const int cur = t & 1, nxt = cur ^ 1;

        // ---- Phase A: h0_new = tanh(a0[t] + h0_cur @ W_hh0) ----
        {
            const float4* src = (const float4*)g_h0buf[cur];
            float4* dst = (float4*)sh0;
#pragma unroll
            for (int i = 0; i < 8; i++) dst[tid + i * 256] = __ldcg(src + tid + i * 256);
        }
        __syncthreads();

        float acc[8];
#pragma unroll
        for (int a = 0; a < 8; a++) acc[a] = 0.f;
#pragma unroll 8
        for (int i = 0; i < 32; i++) {
            int k = kg + (i << 5);
            float w = sw0[k * 8 + jl];
            float4 hA = *(const float4*)(sh0 + k * 8);
            float4 hB = *(const float4*)(sh0 + k * 8 + 4);
            acc[0] += w * hA.x; acc[1] += w * hA.y;
            acc[2] += w * hA.z; acc[3] += w * hA.w;
            acc[4] += w * hB.x; acc[5] += w * hB.y;
            acc[6] += w * hB.z; acc[7] += w * hB.w;
        }
#pragma unroll
        for (int a = 0; a < 8; a++) {
            acc[a] += __shfl_xor_sync(0xffffffffu, acc[a], 8);
            acc[a] += __shfl_xor_sync(0xffffffffu, acc[a], 16);
        }
        if (lane < 8) {
#pragma unroll
            for (int b = 0; b < 8; b++) sred[warp * 64 + jl * 8 + b] = acc[b];
        }
        __syncthreads();
        if (tid < 64) {
            int b = tid >> 3, jj = tid & 7;
            float v = 0.f;
#pragma unroll
            for (int w = 0; w < 8; w++) v += sred[w * 64 + jj * 8 + b];
            v += g_a0[((size_t)t * 8 + b) * H_SZ + j0 + jj];
            float h = tanhf(v);
            __stcg(&g_h0buf[nxt][(j0 + jj) * 8 + b], h);
        }
        grid_barrier();

        // ---- Phase B: h1_new = tanh(h0_new @ W_ih1 + h1_cur @ W_hh1 + b) ----
        {
            const float4* s0 = (const float4*)g_h0buf[nxt];
            const float4* s1 = (const float4*)g_h1buf[cur];
            float4* d0 = (float4*)sh0;
            float4* d1 = (float4*)sh1;
#pragma unroll
            for (int i = 0; i < 8; i++) {
                d0[tid + i * 256] = __ldcg(s0 + tid + i * 256);
                d1[tid + i * 256] = __ldcg(s1 + tid + i * 256);
            }
        }
        __syncthreads();

#pragma unroll
        for (int a = 0; a < 8; a++) acc[a] = 0.f;
#pragma unroll 4
        for (int i = 0; i < 32; i++) {
            int k = kg + (i << 5);
            float w1v = sw1[k * 8 + jl];
            float w2v = sw2[k * 8 + jl];
            float4 aA = *(const float4*)(sh0 + k * 8);
            float4 aB = *(const float4*)(sh0 + k * 8 + 4);
            float4 bA = *(const float4*)(sh1 + k * 8);
            float4 bB = *(const float4*)(sh1 + k * 8 + 4);
            acc[0] += w1v * aA.x; acc[0] += w2v * bA.x;
            acc[1] += w1v * aA.y; acc[1] += w2v * bA.y;
            acc[2] += w1v * aA.z; acc[2] += w2v * bA.z;
            acc[3] += w1v * aA.w; acc[3] += w2v * bA.w;
            acc[4] += w1v * aB.x; acc[4] += w2v * bB.x;
            acc[5] += w1v * aB.y; acc[5] += w2v * bB.y;
            acc[6] += w1v * aB.z; acc[6] += w2v * bB.z;
            acc[7] += w1v * aB.w; acc[7] += w2v * bB.w;
        }
#pragma unroll
        for (int a = 0; a < 8; a++) {
            acc[a] += __shfl_xor_sync(0xffffffffu, acc[a], 8);
            acc[a] += __shfl_xor_sync(0xffffffffu, acc[a], 16);
        }
        if (lane < 8) {
#pragma unroll
            for (int b = 0; b < 8; b++) sred[warp * 64 + jl * 8 + b] = acc[b];
        }
        __syncthreads();
        if (tid < 64) {
            int b = tid >> 3, jj = tid & 7;
            float v = sb[jj];
#pragma unroll
            for (int w = 0; w < 8; w++) v += sred[w * 64 + jj * 8 + b];
            float h = tanhf(v);
            __stcg(&g_h1buf[nxt][(j0 + jj) * 8 + b], h);
            g_outs[((size_t)b * SEQ + t) * H_SZ + j0 + jj] = h;
        }
        grid_barrier();
    }
}

// ---------------------------------------------------------------------------
// Kernel 3: output projection  logits = g_outs @ W_out + b_out
//   M=4096, N=32000, K=1024.  tf32 mma.sync m16n8k8, 128x128x32 tiles,
//   double-buffered SMEM with register prefetch.
// ---------------------------------------------------------------------------
__device__ __forceinline__ float f2tf32(float x)
{
    uint32_t u;
    asm("cvt.rna.tf32.f32 %0, %1;" : "=r"(u) : "f"(x));
    return __uint_as_float(u);
}
__device__ __forceinline__ float4 cvt4(float4 v)
{
    v.x = f2tf32(v.x); v.y = f2tf32(v.y); v.z = f2tf32(v.z); v.w = f2tf32(v.w);
    return v;
}

#define GEMM_SA_STRIDE 36    // 128 rows x 36 (pad) floats
#define GEMM_SB_STRIDE 132   // 32 rows x 132 (pad) floats
#define GEMM_SA_FLOATS (128 * GEMM_SA_STRIDE)   // 4608
#define GEMM_SB_FLOATS (32 * GEMM_SB_STRIDE)    // 4224
#define GEMM_SMEM_BYTES ((2 * GEMM_SA_FLOATS + 2 * GEMM_SB_FLOATS) * 4)  // 70656

__global__ void __launch_bounds__(256, 1) k_out_gemm(
    const float* __restrict__ Wout, const float* __restrict__ bout,
    float* __restrict__ out)
{
    extern __shared__ float sm3[];
    float* sAb = sm3;                         // 2 x 4608
    float* sBb = sm3 + 2 * GEMM_SA_FLOATS;    // 2 x 4224

    const int tid  = threadIdx.x;
    const int n0   = blockIdx.x * 128;
    const int m0   = blockIdx.y * 128;
    const int warp = tid >> 5;
    const int lane = tid & 31;
    const int g    = lane >> 2;
    const int tg   = lane & 3;
    const int wm   = warp & 3;   // 4 warps along M (32 rows each)
    const int wn   = warp >> 2;  // 2 warps along N (64 cols each)

    float acc[2][8][4];
#pragma unroll
    for (int mt = 0; mt < 2; mt++)
#pragma unroll
        for (int nt = 0; nt < 8; nt++)
#pragma unroll
            for (int q = 0; q < 4; q++) acc[mt][nt][q] = 0.f;

    float4 ra[4], rb[4];
    const int arow = tid >> 3, ac4 = tid & 7;     // A staging coords
    const int bkr  = tid >> 5, bc4 = tid & 31;    // B staging coords

    // prologue: load k-tile 0 into regs, store to buffer 0
#pragma unroll
    for (int i = 0; i < 4; i++)
        ra[i] = *(const float4*)(g_outs + (size_t)(m0 + arow + i * 32) * H_SZ + ac4 * 4);
#pragma unroll
    for (int i = 0; i < 4; i++)
        rb[i] = *(const float4*)(Wout + (size_t)(bkr + i * 8) * V_SZ + n0 + bc4 * 4);
#pragma unroll
    for (int i = 0; i < 4; i++)
        *(float4*)(sAb + (arow + i * 32) * GEMM_SA_STRIDE + ac4 * 4) = cvt4(ra[i]);
#pragma unroll
    for (int i = 0; i < 4; i++)
        *(float4*)(sBb + (bkr + i * 8) * GEMM_SB_STRIDE + bc4 * 4) = cvt4(rb[i]);
    __syncthreads();

    for (int kt = 0; kt < 32; kt++) {
        const int buf = kt & 1;
        const float* A = sAb + buf * GEMM_SA_FLOATS;
        const float* B = sBb + buf * GEMM_SB_FLOATS;

        if (kt < 31) {
            const int k0 = (kt + 1) * 32;
#pragma unroll
            for (int i = 0; i < 4; i++)
                ra[i] = *(const float4*)(g_outs + (size_t)(m0 + arow + i * 32) * H_SZ + k0 + ac4 * 4);
#pragma unroll
            for (int i = 0; i < 4; i++)
                rb[i] = *(const float4*)(Wout + (size_t)(k0 + bkr + i * 8) * V_SZ + n0 + bc4 * 4);
        }

#pragma unroll
        for (int kk = 0; kk < 4; kk++) {
            const int k8 = kk * 8;
            uint32_t af[2][4];
#pragma unroll
            for (int mt = 0; mt < 2; mt++) {
                int r = wm * 32 + mt * 16 + g;
                af[mt][0] = __float_as_uint(A[r * GEMM_SA_STRIDE + k8 + tg]);
                af[mt][1] = __float_as_uint(A[(r + 8) * GEMM_SA_STRIDE + k8 + tg]);
                af[mt][2] = __float_as_uint(A[r * GEMM_SA_STRIDE + k8 + tg + 4]);
                af[mt][3] = __float_as_uint(A[(r + 8) * GEMM_SA_STRIDE + k8 + tg + 4]);
            }
            uint32_t bf[8][2];
#pragma unroll
            for (int nt = 0; nt < 8; nt++) {
                int c = wn * 64 + nt * 8 + g;
                bf[nt][0] = __float_as_uint(B[(k8 + tg) * GEMM_SB_STRIDE + c]);
                bf[nt][1] = __float_as_uint(B[(k8 + tg + 4) * GEMM_SB_STRIDE + c]);
            }
#pragma unroll
            for (int mt = 0; mt < 2; mt++)
#pragma unroll
                for (int nt = 0; nt < 8; nt++) {
                    asm volatile(
                        "mma.sync.aligned.m16n8k8.row.col.f32.tf32.tf32.f32 "
                        "{%0,%1,%2,%3},{%4,%5,%6,%7},{%8,%9},{%0,%1,%2,%3};\n"
                        : "+f"(acc[mt][nt][0]), "+f"(acc[mt][nt][1]),
                          "+f"(acc[mt][nt][2]), "+f"(acc[mt][nt][3])
                        : "r"(af[mt][0]), "r"(af[mt][1]), "r"(af[mt][2]), "r"(af[mt][3]),
                          "r"(bf[nt][0]), "r"(bf[nt][1]));
                }
        }

        if (kt < 31) {
            float* An = sAb + (buf ^ 1) * GEMM_SA_FLOATS;
            float* Bn = sBb + (buf ^ 1) * GEMM_SB_FLOATS;
#pragma unroll
            for (int i = 0; i < 4; i++)
                *(float4*)(An + (arow + i * 32) * GEMM_SA_STRIDE + ac4 * 4) = cvt4(ra[i]);
#pragma unroll
            for (int i = 0; i < 4; i++)
                *(float4*)(Bn + (bkr + i * 8) * GEMM_SB_STRIDE + bc4 * 4) = cvt4(rb[i]);
        }
        __syncthreads();
    }

    // epilogue: add bias, write logits
#pragma unroll
    for (int nt = 0; nt < 8; nt++) {
        int c = n0 + wn * 64 + nt * 8 + 2 * tg;
        float b0 = bout[c], b1 = bout[c + 1];
#pragma unroll
        for (int mt = 0; mt < 2; mt++) {
            int r = m0 + wm * 32 + mt * 16 + g;
            float2 v0 = make_float2(acc[mt][nt][0] + b0, acc[mt][nt][1] + b1);
            float2 v1 = make_float2(acc[mt][nt][2] + b0, acc[mt][nt][3] + b1);
            *(float2*)(out + (size_t)r * V_SZ + c) = v0;
            *(float2*)(out + (size_t)(r + 8) * V_SZ + c) = v1;
        }
    }
}

// ---------------------------------------------------------------------------
// Kernel 4: write final hidden states h0, h1 after logits
// ---------------------------------------------------------------------------
__global__ void __launch_bounds__(256) k_tail(float* __restrict__ out)
{
    int idx = blockIdx.x * 256 + threadIdx.x;
    if (idx < BATCH * H_SZ) {
        int b = idx >> 10, j = idx & 1023;
        // after 512 steps, final state lives in buffer (512 & 1) = 0
        out[LOGITS + idx]                 = g_h0buf[0][j * 8 + b];
        out[LOGITS + BATCH * H_SZ + idx]  = g_h1buf[0][j * 8 + b];
    }
}

// ---------------------------------------------------------------------------
// Launch
// ---------------------------------------------------------------------------
extern "C" void kernel_launch(void* const* d_in, const int* in_sizes, int n_in,
                              void* d_out, int out_size)
{
    const int*   x     = (const int*)  d_in[0];
    const float* emb   = (const float*)d_in[1];
    const float* W_ih0 = (const float*)d_in[2];
    const float* b_ih0 = (const float*)d_in[3];
    const float* W_hh0 = (const float*)d_in[4];
    const float* b_hh0 = (const float*)d_in[5];
    const float* W_ih1 = (const float*)d_in[6];
    const float* b_ih1 = (const float*)d_in[7];
    const float* W_hh1 = (const float*)d_in[8];
    const float* b_hh1 = (const float*)d_in[9];
    const float* W_out = (const float*)d_in[10];
    const float* b_out = (const float*)d_in[11];
    float* out = (float*)d_out;

    cudaFuncSetAttribute(k_rnn, cudaFuncAttributeMaxDynamicSharedMemorySize,
                         RNN_SMEM_BYTES);
    cudaFuncSetAttribute(k_out_gemm, cudaFuncAttributeMaxDynamicSharedMemorySize,
                         GEMM_SMEM_BYTES);

    // 1) input-term GEMM:  grid (N tiles=16, M tiles=64)
    k_embed_gemm<<<dim3(16, 64), 256>>>(x, emb, W_ih0, b_ih0, b_hh0);

    // 2) persistent recurrence: exactly 128 co-resident CTAs
    k_rnn<<<NCTA, 256, RNN_SMEM_BYTES>>>(W_hh0, W_ih1, W_hh1, b_ih1, b_hh1);

    // 3) output projection: grid (N tiles=250, M tiles=32)
    k_out_gemm<<<dim3(250, 32), 256, GEMM_SMEM_BYTES>>>(W_out, b_out, out);

    // 4) final hidden states
    k_tail<<<32, 256>>>(out);
}

// round 2
// speedup vs baseline: 1.5285x; 1.5285x over previous
#include <cuda_runtime.h>
#include <cuda_bf16.h>
#include <cstdint>
#include <cstddef>

// ---------------------------------------------------------------------------
// Problem constants
// ---------------------------------------------------------------------------
#define V_SZ   32000
#define E_DIM  256
#define H_SZ   1024
#define BATCH  8
#define SEQ    512
#define ROWS   (BATCH*SEQ)          // 4096
#define LOGITS ((size_t)ROWS*V_SZ)  // 131072000

// ---------------------------------------------------------------------------
// Device scratch (static allocation — no cudaMalloc allowed)
// ---------------------------------------------------------------------------
__device__ float g_a0[(size_t)ROWS * H_SZ];     // input term [t*8+b][h]
__device__ float g_outs[(size_t)ROWS * H_SZ];   // h1 per step (tf32-rounded), row r=b*512+t
__device__ float g_wout[(size_t)H_SZ * V_SZ];   // tf32-rounded copy of W_out
__device__ float g_h0buf[2][H_SZ * BATCH];      // [j*8+b] layout
__device__ float g_h1buf[2][H_SZ * BATCH];
__device__ unsigned          g_barc = 0;
__device__ volatile unsigned g_barg = 0;

// ---------------------------------------------------------------------------
// Small helpers
// ---------------------------------------------------------------------------
__device__ __forceinline__ float f2tf32(float x)
{
    uint32_t u;
    asm("cvt.rna.tf32.f32 %0, %1;" : "=r"(u) : "f"(x));
    return __uint_as_float(u);
}
__device__ __forceinline__ float4 cvt4(float4 v)
{
    v.x = f2tf32(v.x); v.y = f2tf32(v.y); v.z = f2tf32(v.z); v.w = f2tf32(v.w);
    return v;
}
__device__ __forceinline__ unsigned long long fma2(
    unsigned long long a, unsigned long long b, unsigned long long c)
{
    unsigned long long d;
    asm("fma.rn.f32x2 %0, %1, %2, %3;" : "=l"(d) : "l"(a), "l"(b), "l"(c));
    return d;
}
__device__ __forceinline__ unsigned long long pack2(float w)
{
    unsigned long long d;
    asm("mov.b64 %0, {%1, %1};" : "=l"(d) : "r"(__float_as_uint(w)));
    return d;
}
__device__ __forceinline__ void unpack2(unsigned long long v, float& lo, float& hi)
{
    uint32_t l, h;
    asm("mov.b64 {%0, %1}, %2;" : "=r"(l), "=r"(h) : "l"(v));
    lo = __uint_as_float(l); hi = __uint_as_float(h);
}
__device__ __forceinline__ void cp16(float* s, const float* g)
{
    unsigned sa = (unsigned)__cvta_generic_to_shared(s);
    asm volatile("cp.async.cg.shared.global [%0], [%1], 16;" :: "r"(sa), "l"(g));
}
#define CP_COMMIT() asm volatile("cp.async.commit_group;")
#define CP_WAIT2()  asm volatile("cp.async.wait_group 2;")

// ---------------------------------------------------------------------------
// Kernel 0: pre-round W_out to tf32 (rna) into g_wout
// ---------------------------------------------------------------------------
__global__ void __launch_bounds__(256) k_cvt(const float* __restrict__ W)
{
    size_t i = ((size_t)blockIdx.x * 256 + threadIdx.x) * 4;
    float4 v = *(const float4*)(W + i);
    *(float4*)(g_wout + i) = cvt4(v);
}

// ---------------------------------------------------------------------------
// Kernel 1: embedding gather + input GEMM
//   g_a0[(t*8+b)*H + j] = emb[x[b,t]] @ W_ih0[:,j] + b_ih0[j] + b_hh0[j]
// ---------------------------------------------------------------------------
__global__ void __launch_bounds__(256) k_embed_gemm(
    const int* __restrict__ x, const float* __restrict__ emb,
    const float* __restrict__ Wih0, const float* __restrict__ bih0,
    const float* __restrict__ bhh0)
{
    __shared__ float sA[64][68];
    __shared__ float sB[64][68];
    const int n0 = blockIdx.x * 64;
    const int m0 = blockIdx.y * 64;
    const int tid = threadIdx.x;
    const int ty = tid >> 4, tx = tid & 15;

    float acc[4][4];
#pragma unroll
    for (int i = 0; i < 4; i++)
#pragma unroll
        for (int j = 0; j < 4; j++) acc[i][j] = 0.f;

    for (int k0 = 0; k0 < E_DIM; k0 += 64) {
#pragma unroll
        for (int i = 0; i < 4; i++) {
            int r  = (tid >> 4) + i * 16;
            int c4 = tid & 15;
            int rg = m0 + r;
            int t  = rg >> 3, b = rg & 7;
            int tok = x[b * SEQ + t];
            float4 v = *(const float4*)(emb + (size_t)tok * E_DIM + k0 + c4 * 4);
            *(float4*)&sA[r][c4 * 4] = v;
        }
#pragma unroll
        for (int i = 0; i < 4; i++) {
            int kr = (tid >> 4) + i * 16;
            int c4 = tid & 15;
            float4 v = *(const float4*)(Wih0 + (size_t)(k0 + kr) * H_SZ + n0 + c4 * 4);
            *(float4*)&sB[kr][c4 * 4] = v;
        }
        __syncthreads();
#pragma unroll 8
        for (int k = 0; k < 64; k++) {
            float a[4], bb[4];
#pragma unroll
            for (int i = 0; i < 4; i++) a[i] = sA[ty * 4 + i][k];
#pragma unroll
            for (int j = 0; j < 4; j++) bb[j] = sB[k][tx * 4 + j];
#pragma unroll
            for (int i = 0; i < 4; i++)
#pragma unroll
                for (int j = 0; j < 4; j++) acc[i][j] += a[i] * bb[j];
        }
        __syncthreads();
    }
#pragma unroll
    for (int i = 0; i < 4; i++) {
        int r = m0 + ty * 4 + i;
#pragma unroll
        for (int j = 0; j < 4; j++) {
            int n = n0 + tx * 4 + j;
            g_a0[(size_t)r * H_SZ + n] = acc[i][j] + bih0[n] + bhh0[n];
        }
    }
}

// ---------------------------------------------------------------------------
// Kernel 2: persistent pipelined recurrence.
//   Superstep s (0..512): H0(s+1)=tanh(a0[s]+H0(s)W0)  [s<512]
//                         H1(s)  =tanh(H0(s)W1+H1(s-1)W2+b) [s>=1]
//   ONE grid barrier per superstep. fp32x2 packed FMA inner loop.
// ---------------------------------------------------------------------------
#define NCTA 128

__device__ __forceinline__ void grid_barrier()
{
    __syncthreads();
    __threadfence();
    if (threadIdx.x == 0) {
        unsigned gen = g_barg;
        unsigned a = atomicAdd(&g_barc, 1u);
        if (a == NCTA - 1) {
            g_barc = 0;
            __threadfence();
            g_barg = gen + 1;
        } else {
            while (g_barg == gen) { }
        }
    }
    __syncthreads();
}

// SMEM (floats): sw0[8192] sw1[8192] sw2[8192] sh0[8192] sh1[8192]
//                sred[1024] sb[8]  = 41992 floats = 167,968 B
#define RNN_SMEM_FLOATS 41992
#define RNN_SMEM_BYTES  (RNN_SMEM_FLOATS * 4)

__global__ void __launch_bounds__(256, 1) k_rnn(
    const float* __restrict__ Whh0, const float* __restrict__ Wih1,
    const float* __restrict__ Whh1, const float* __restrict__ bih1,
    const float* __restrict__ bhh1)
{
    extern __shared__ float sm[];
    float* sw0  = sm;
    float* sw1  = sm + 8192;
    float* sw2  = sm + 16384;
    float* sh0  = sm + 24576;
    float* sh1  = sm + 32768;
    float* sred = sm + 40960;   // 1024 (two sets of 512)
    float* sb   = sm + 41984;   // 8

    const int tid  = threadIdx.x;
    const int j0   = blockIdx.x * 8;
    const int jl   = tid & 7;
    const int kg   = tid >> 3;       // 0..31
    const int lane = tid & 31;
    const int warp = tid >> 5;

    // weight slices: sw[k*8+jl] = W[k][j0+jl]
    for (int idx = tid; idx < 8192; idx += 256) {
        int jj = idx & 7, k = idx >> 3;
        sw0[idx] = Whh0[(size_t)k * H_SZ + j0 + jj];
        sw1[idx] = Wih1[(size_t)k * H_SZ + j0 + jj];
        sw2[idx] = Whh1[(size_t)k * H_SZ + j0 + jj];
    }
    if (tid < 8) sb[tid] = bih1[j0 + tid] + bhh1[j0 + tid];

    // zero initial state in ALL buffers (each CTA its 64-float slice)
    if (tid < 64) {
        int o = blockIdx.x * 64 + tid;
        __stcg(&g_h0buf[0][o], 0.f); __stcg(&g_h0buf[1][o], 0.f);
        __stcg(&g_h1buf[0][o], 0.f); __stcg(&g_h1buf[1][o], 0.f);
    }
    grid_barrier();

    for (int s = 0; s <= SEQ; s++) {
        // prefetch a0 term for layer-0 (hidden behind inner loop)
        float a0v = 0.f;
        if (tid < 64 && s < SEQ) {
            int b = tid >> 3, jj = tid & 7;
            a0v = __ldcg(&g_a0[((size_t)s * 8 + b) * H_SZ + j0 + jj]);
        }

        // load H0(s) [buf s&1] and H1(s-1) [buf (s+1)&1] once into smem
        {
            const float4* s0 = (const float4*)g_h0buf[s & 1];
            const float4* s1 = (const float4*)g_h1buf[(s + 1) & 1];
            float4* d0 = (float4*)sh0;
            float4* d1 = (float4*)sh1;
#pragma unroll
            for (int i = 0; i < 8; i++) {
                d0[tid + i * 256] = __ldcg(s0 + tid + i * 256);
                d1[tid + i * 256] = __ldcg(s1 + tid + i * 256);
            }
        }
        __syncthreads();

        // packed f32x2 inner loop: c0 = layer0 acc, c1 = layer1 acc (8 floats each)
        unsigned long long c0[4] = {0ull, 0ull, 0ull, 0ull};
        unsigned long long c1[4] = {0ull, 0ull, 0ull, 0ull};
#pragma unroll 4
        for (int i = 0; i < 32; i++) {
            const int k    = kg + (i << 5);
            const int wadr = tid + (i << 8);
            unsigned long long W0 = pack2(sw0[wadr]);
            unsigned long long W1 = pack2(sw1[wadr]);
            unsigned long long W2 = pack2(sw2[wadr]);
            const ulonglong2* hp = (const ulonglong2*)(sh0 + k * 8);
            const ulonglong2* hq = (const ulonglong2*)(sh1 + k * 8);
            ulonglong2 p0 = hp[0], p1 = hp[1];
            ulonglong2 q0 = hq[0], q1 = hq[1];
            c0[0] = fma2(W0, p0.x, c0[0]); c0[1] = fma2(W0, p0.y, c0[1]);
            c0[2] = fma2(W0, p1.x, c0[2]); c0[3] = fma2(W0, p1.y, c0[3]);
            c1[0] = fma2(W1, p0.x, c1[0]); c1[1] = fma2(W1, p0.y, c1[1]);
            c1[2] = fma2(W1, p1.x, c1[2]); c1[3] = fma2(W1, p1.y, c1[3]);
            c1[0] = fma2(W2, q0.x, c1[0]); c1[1] = fma2(W2, q0.y, c1[1]);
            c1[2] = fma2(W2, q1.x, c1[2]); c1[3] = fma2(W2, q1.y, c1[3]);
        }
        float a0[8], a1[8];
#pragma unroll
        for (int q = 0; q < 4; q++) {
            unpack2(c0[q], a0[q * 2], a0[q * 2 + 1]);
            unpack2(c1[q], a1[q * 2], a1[q * 2 + 1]);
        }
        // reduce over kg within warp (kg differs in bits 3,4 of lane)
#pragma unroll
        for (int q = 0; q < 8; q++) {
            a0[q] += __shfl_xor_sync(0xffffffffu, a0[q], 8);
            a0[q] += __shfl_xor_sync(0xffffffffu, a0[q], 16);
            a1[q] += __shfl_xor_sync(0xffffffffu, a1[q], 8);
            a1[q] += __shfl_xor_sync(0xffffffffu, a1[q], 16);
        }
        if (lane < 8) {   // lane == jl here
#pragma unroll
            for (int b = 0; b < 8; b++) {
                sred[warp * 64 + lane * 8 + b]       = a0[b];
                sred[512 + warp * 64 + lane * 8 + b] = a1[b];
            }
        }
        __syncthreads();

        if (tid < 128) {
            const int set = tid >> 6;
            const int o   = tid & 63;
            const int b   = o >> 3, jj = o & 7;
            float v = 0.f;
#pragma unroll
            for (int w = 0; w < 8; w++) v += sred[set * 512 + w * 64 + jj * 8 + b];
            if (set == 0) {
                if (s < SEQ) {
                    float h = tanhf(v + a0v);
                    __stcg(&g_h0buf[(s + 1) & 1][(j0 + jj) * 8 + b], h);
                }
            } else {
                if (s >= 1) {
                    float h = tanhf(v + sb[jj]);
                    __stcg(&g_h1buf[s & 1][(j0 + jj) * 8 + b], h);
                    g_outs[((size_t)b * SEQ + (s - 1)) * H_SZ + j0 + jj] = f2tf32(h);
                }
            }
        }
        if (s < SEQ) grid_barrier();
    }
}

// ---------------------------------------------------------------------------
// Kernel 3: output projection  logits = g_outs @ g_wout + b_out
//   M=4096, N=32000, K=1024. 256x128x32 tiles, 64x64 warp tiles,
//   tf32 mma m16n8k8, 3-stage cp.async pipeline. m-fast rasterization.
// ---------------------------------------------------------------------------
#define TM 256
#define TN 128
#define TK 32
#define SA_STRIDE 36
#define SB_STRIDE 132
#define SA_FLOATS (TM * SA_STRIDE)   // 9216
#define SB_FLOATS (TK * SB_STRIDE)   // 4224
#define NSTAGE 3
#define GEMM_SMEM_BYTES (NSTAGE * (SA_FLOATS + SB_FLOATS) * 4)  // 161280

__device__ __forceinline__ void gemm_stage(
    int kt, float* sA, float* sB, int m0, int n0, int tid)
{
    const int k0 = kt * TK;
    const int ar = tid >> 3, ac = (tid & 7) * 4;
#pragma unroll
    for (int i = 0; i < 8; i++)
        cp16(sA + (ar + i * 32) * SA_STRIDE + ac,
             g_outs + (size_t)(m0 + ar + i * 32) * H_SZ + k0 + ac);
    const int br = tid >> 5, bc = (tid & 31) * 4;
#pragma unroll
    for (int i = 0; i < 4; i++)
        cp16(sB + (br + i * 8) * SB_STRIDE + bc,
             g_wout + (size_t)(k0 + br + i * 8) * V_SZ + n0 + bc);
}

__global__ void __launch_bounds__(256, 1) k_out_gemm(
    const float* __restrict__ bout, float* __restrict__ out)
{
    extern __shared__ float sm3[];
    float* sA = sm3;                          // NSTAGE x 9216
    float* sB = sm3 + NSTAGE * SA_FLOATS;     // NSTAGE x 4224

    const int tid  = threadIdx.x;
    const int m0   = blockIdx.x * TM;   // m-fast: B tiles reused 16x via L2
    const int n0   = blockIdx.y * TN;
    const int warp = tid >> 5;
    const int lane = tid & 31;
    const int g    = lane >> 2;
    const int tg   = lane & 3;
    const int wm   = warp & 3;   // 4 warps along M (64 rows each)
    const int wn   = warp >> 2;  // 2 warps along N (64 cols each)

    float acc[4][8][4];
#pragma unroll
    for (int mt = 0; mt < 4; mt++)
#pragma unroll
        for (int nt = 0; nt < 8; nt++)
#pragma unroll
            for (int q = 0; q < 4; q++) acc[mt][nt][q] = 0.f;

    // prologue: stages 0 and 1
    gemm_stage(0, sA, sB, m0, n0, tid);
    CP_COMMIT();
    gemm_stage(1, sA + SA_FLOATS, sB + SB_FLOATS, m0, n0, tid);
    CP_COMMIT();

    for (int kt = 0; kt < 32; kt++) {
        // issue stage kt+2 (buffer freed by the __syncthreads at end of kt-1)
        if (kt + 2 < 32) {
            int st = (kt + 2) % NSTAGE;
            gemm_stage(kt + 2, sA + st * SA_FLOATS, sB + st * SB_FLOATS, m0, n0, tid);
        }
        CP_COMMIT();
        CP_WAIT2();          // all but the 2 newest groups done -> stage kt ready
        __syncthreads();

        const float* A = sA + (kt % NSTAGE) * SA_FLOATS;
        const float* B = sB + (kt % NSTAGE) * SB_FLOATS;
#pragma unroll
        for (int kk = 0; kk < 4; kk++) {
            const int k8 = kk * 8;
            uint32_t af[4][4];
#pragma unroll
            for (int mt = 0; mt < 4; mt++) {
                int r = wm * 64 + mt * 16 + g;
                af[mt][0] = __float_as_uint(A[r * SA_STRIDE + k8 + tg]);
                af[mt][1] = __float_as_uint(A[(r + 8) * SA_STRIDE + k8 + tg]);
                af[mt][2] = __float_as_uint(A[r * SA_STRIDE + k8 + tg + 4]);
                af[mt][3] = __float_as_uint(A[(r + 8) * SA_STRIDE + k8 + tg + 4]);
            }
            uint32_t bf[8][2];
#pragma unroll
            for (int nt = 0; nt < 8; nt++) {
                int c = wn * 64 + nt * 8 + g;
                bf[nt][0] = __float_as_uint(B[(k8 + tg) * SB_STRIDE + c]);
                bf[nt][1] = __float_as_uint(B[(k8 + tg + 4) * SB_STRIDE + c]);
            }
#pragma unroll
            for (int mt = 0; mt < 4; mt++)
#pragma unroll
                for (int nt = 0; nt < 8; nt++) {
                    asm volatile(
                        "mma.sync.aligned.m16n8k8.row.col.f32.tf32.tf32.f32 "
                        "{%0,%1,%2,%3},{%4,%5,%6,%7},{%8,%9},{%0,%1,%2,%3};\n"
                        : "+f"(acc[mt][nt][0]), "+f"(acc[mt][nt][1]),
                          "+f"(acc[mt][nt][2]), "+f"(acc[mt][nt][3])
                        : "r"(af[mt][0]), "r"(af[mt][1]), "r"(af[mt][2]), "r"(af[mt][3]),
                          "r"(bf[nt][0]), "r"(bf[nt][1]));
                }
        }
        __syncthreads();   // all warps done with stage kt before it is re-filled
    }

    // epilogue: bias + store
#pragma unroll
    for (int nt = 0; nt < 8; nt++) {
        int c = n0 + wn * 64 + nt * 8 + 2 * tg;
        float b0 = bout[c], b1 = bout[c + 1];
#pragma unroll
        for (int mt = 0; mt < 4; mt++) {
            int r = m0 + wm * 64 + mt * 16 + g;
            float2 v0 = make_float2(acc[mt][nt][0] + b0, acc[mt][nt][1] + b1);
            float2 v1 = make_float2(acc[mt][nt][2] + b0, acc[mt][nt][3] + b1);
            *(float2*)(out + (size_t)r * V_SZ + c) = v0;
            *(float2*)(out + (size_t)(r + 8) * V_SZ + c) = v1;
        }
    }
}

// ---------------------------------------------------------------------------
// Kernel 4: final hidden states h0, h1 (both end in buffer 0 after 512 steps)
// ---------------------------------------------------------------------------
__global__ void __launch_bounds__(256) k_tail(float* __restrict__ out)
{
    int idx = blockIdx.x * 256 + threadIdx.x;
    if (idx < BATCH * H_SZ) {
        int b = idx >> 10, j = idx & 1023;
        out[LOGITS + idx]                = g_h0buf[0][j * 8 + b];
        out[LOGITS + BATCH * H_SZ + idx] = g_h1buf[0][j * 8 + b];
    }
}

// ---------------------------------------------------------------------------
// Launch
// ---------------------------------------------------------------------------
extern "C" void kernel_launch(void* const* d_in, const int* in_sizes, int n_in,
                              void* d_out, int out_size)
{
    const int*   x     = (const int*)  d_in[0];
    const float* emb   = (const float*)d_in[1];
    const float* W_ih0 = (const float*)d_in[2];
    const float* b_ih0 = (const float*)d_in[3];
    const float* W_hh0 = (const float*)d_in[4];
    const float* b_hh0 = (const float*)d_in[5];
    const float* W_ih1 = (const float*)d_in[6];
    const float* b_ih1 = (const float*)d_in[7];
    const float* W_hh1 = (const float*)d_in[8];
    const float* b_hh1 = (const float*)d_in[9];
    const float* W_out = (const float*)d_in[10];
    const float* b_out = (const float*)d_in[11];
    float* out = (float*)d_out;

    cudaFuncSetAttribute(k_rnn, cudaFuncAttributeMaxDynamicSharedMemorySize,
                         RNN_SMEM_BYTES);
    cudaFuncSetAttribute(k_out_gemm, cudaFuncAttributeMaxDynamicSharedMemorySize,
                         GEMM_SMEM_BYTES);

    // 0) tf32 pre-round of W_out (independent of 1-2)
    k_cvt<<<32000, 256>>>(W_out);

    // 1) input-term GEMM
    k_embed_gemm<<<dim3(16, 64), 256>>>(x, emb, W_ih0, b_ih0, b_hh0);

    // 2) pipelined persistent recurrence (128 co-resident CTAs)
    k_rnn<<<NCTA, 256, RNN_SMEM_BYTES>>>(W_hh0, W_ih1, W_hh1, b_ih1, b_hh1);

    // 3) output projection, m-fast rasterization: grid (m=16, n=250)
    k_out_gemm<<<dim3(16, 250), 256, GEMM_SMEM_BYTES>>>(b_out, out);

    // 4) final hidden states
    k_tail<<<32, 256>>>(out);
}

// round 4
// speedup vs baseline: 1.6409x; 1.0735x over previous
#include <cuda_runtime.h>
#include <cuda_bf16.h>
#include <cstdint>
#include <cstddef>

// ---------------------------------------------------------------------------
// Problem constants
// ---------------------------------------------------------------------------
#define V_SZ   32000
#define E_DIM  256
#define H_SZ   1024
#define BATCH  8
#define SEQ    512
#define ROWS   (BATCH*SEQ)          // 4096
#define LOGITS ((size_t)ROWS*V_SZ)  // 131072000

// ---------------------------------------------------------------------------
// Device scratch (static allocation — no cudaMalloc allowed)
// ---------------------------------------------------------------------------
__device__ float g_a0[(size_t)ROWS * H_SZ];     // input term [t*8+b][h]
__device__ float g_outs[(size_t)ROWS * H_SZ];   // h1 per step (tf32-rounded), row r=b*512+t
__device__ float g_wout[(size_t)H_SZ * V_SZ];   // tf32-rounded copy of W_out
__device__ float g_h0buf[2][H_SZ * BATCH];      // [j*8+b] layout
__device__ float g_h1buf[2][H_SZ * BATCH];
__device__ unsigned          g_barc = 0;
__device__ volatile unsigned g_barg = 0;

// ---------------------------------------------------------------------------
// Small helpers
// ---------------------------------------------------------------------------
__device__ __forceinline__ float f2tf32(float x)
{
    uint32_t u;
    asm("cvt.rna.tf32.f32 %0, %1;" : "=r"(u) : "f"(x));
    return __uint_as_float(u);
}
__device__ __forceinline__ float4 cvt4(float4 v)
{
    v.x = f2tf32(v.x); v.y = f2tf32(v.y); v.z = f2tf32(v.z); v.w = f2tf32(v.w);
    return v;
}
__device__ __forceinline__ unsigned long long fma2(
    unsigned long long a, unsigned long long b, unsigned long long c)
{
    unsigned long long d;
    asm("fma.rn.f32x2 %0, %1, %2, %3;" : "=l"(d) : "l"(a), "l"(b), "l"(c));
    return d;
}
__device__ __forceinline__ unsigned long long pack2(float w)
{
    unsigned long long d;
    asm("mov.b64 %0, {%1, %1};" : "=l"(d) : "r"(__float_as_uint(w)));
    return d;
}
__device__ __forceinline__ void unpack2(unsigned long long v, float& lo, float& hi)
{
    uint32_t l, h;
    asm("mov.b64 {%0, %1}, %2;" : "=r"(l), "=r"(h) : "l"(v));
    lo = __uint_as_float(l); hi = __uint_as_float(h);
}
__device__ __forceinline__ void cp16(float* s, const float* g)
{
    unsigned sa = (unsigned)__cvta_generic_to_shared(s);
    asm volatile("cp.async.cg.shared.global [%0], [%1], 16;" :: "r"(sa), "l"(g));
}
#define CP_COMMIT() asm volatile("cp.async.commit_group;")
#define CP_WAIT2()  asm volatile("cp.async.wait_group 2;")

// ---------------------------------------------------------------------------
// Kernel 0: pre-round W_out to tf32 (rna) into g_wout
// ---------------------------------------------------------------------------
__global__ void __launch_bounds__(256) k_cvt(const float* __restrict__ W)
{
    size_t i = ((size_t)blockIdx.x * 256 + threadIdx.x) * 4;
    float4 v = *(const float4*)(W + i);
    *(float4*)(g_wout + i) = cvt4(v);
}

// ---------------------------------------------------------------------------
// Kernel 1: embedding gather + input GEMM
// ---------------------------------------------------------------------------
__global__ void __launch_bounds__(256) k_embed_gemm(
    const int* __restrict__ x, const float* __restrict__ emb,
    const float* __restrict__ Wih0, const float* __restrict__ bih0,
    const float* __restrict__ bhh0)
{
    __shared__ float sA[64][68];
    __shared__ float sB[64][68];
    const int n0 = blockIdx.x * 64;
    const int m0 = blockIdx.y * 64;
    const int tid = threadIdx.x;
    const int ty = tid >> 4, tx = tid & 15;

    float acc[4][4];
#pragma unroll
    for (int i = 0; i < 4; i++)
#pragma unroll
        for (int j = 0; j < 4; j++) acc[i][j] = 0.f;

    for (int k0 = 0; k0 < E_DIM; k0 += 64) {
#pragma unroll
        for (int i = 0; i < 4; i++) {
            int r  = (tid >> 4) + i * 16;
            int c4 = tid & 15;
            int rg = m0 + r;
            int t  = rg >> 3, b = rg & 7;
            int tok = x[b * SEQ + t];
            float4 v = *(const float4*)(emb + (size_t)tok * E_DIM + k0 + c4 * 4);
            *(float4*)&sA[r][c4 * 4] = v;
        }
#pragma unroll
        for (int i = 0; i < 4; i++) {
            int kr = (tid >> 4) + i * 16;
            int c4 = tid & 15;
            float4 v = *(const float4*)(Wih0 + (size_t)(k0 + kr) * H_SZ + n0 + c4 * 4);
            *(float4*)&sB[kr][c4 * 4] = v;
        }
        __syncthreads();
#pragma unroll 8
        for (int k = 0; k < 64; k++) {
            float a[4], bb[4];
#pragma unroll
            for (int i = 0; i < 4; i++) a[i] = sA[ty * 4 + i][k];
#pragma unroll
            for (int j = 0; j < 4; j++) bb[j] = sB[k][tx * 4 + j];
#pragma unroll
            for (int i = 0; i < 4; i++)
#pragma unroll
                for (int j = 0; j < 4; j++) acc[i][j] += a[i] * bb[j];
        }
        __syncthreads();
    }
#pragma unroll
    for (int i = 0; i < 4; i++) {
        int r = m0 + ty * 4 + i;
#pragma unroll
        for (int j = 0; j < 4; j++) {
            int n = n0 + tx * 4 + j;
            g_a0[(size_t)r * H_SZ + n] = acc[i][j] + bih0[n] + bhh0[n];
        }
    }
}

// ---------------------------------------------------------------------------
// Kernel 2: persistent pipelined recurrence.
//   Superstep s (0..512): H0(s+1)=tanh(a0[s]+H0(s)W0)  [s<512]
//                         H1(s)  =tanh(H0(s)W1+H1(s-1)W2+b) [s>=1]
//   Weights live in REGISTERS (96 per thread, constant across supersteps).
//   Central atomic grid barrier (proven), one per superstep.
// ---------------------------------------------------------------------------
#define NCTA 128

__device__ __forceinline__ void grid_barrier()
{
    __syncthreads();
    __threadfence();
    if (threadIdx.x == 0) {
        unsigned gen = g_barg;
        unsigned a = atomicAdd(&g_barc, 1u);
        if (a == NCTA - 1) {
            g_barc = 0;
            __threadfence();
            g_barg = gen + 1;
        } else {
            while (g_barg == gen) { }
        }
    }
    __syncthreads();
}

// SMEM (floats): sh0[8192] sh1[8192] sred[1024] sb[8] = 17416 floats = 69,664 B
#define RNN_SMEM_FLOATS 17416
#define RNN_SMEM_BYTES  (RNN_SMEM_FLOATS * 4)

__global__ void __launch_bounds__(256, 1) k_rnn(
    const float* __restrict__ Whh0, const float* __restrict__ Wih1,
    const float* __restrict__ Whh1, const float* __restrict__ bih1,
    const float* __restrict__ bhh1)
{
    extern __shared__ float sm[];
    float* sh0  = sm;
    float* sh1  = sm + 8192;
    float* sred = sm + 16384;   // 1024 (two sets of 512)
    float* sb   = sm + 17408;   // 8

    const int tid  = threadIdx.x;
    const int j0   = blockIdx.x * 8;
    const int jl   = tid & 7;
    const int kg   = tid >> 3;       // 0..31
    const int lane = tid & 31;
    const int warp = tid >> 5;

    // weight slices into REGISTERS: Wr[i] = W[kg+32i][j0+jl]
    float W0r[32], W1r[32], W2r[32];
#pragma unroll
    for (int i = 0; i < 32; i++) {
        size_t off = (size_t)(kg + 32 * i) * H_SZ + j0 + jl;
        W0r[i] = Whh0[off];
        W1r[i] = Wih1[off];
        W2r[i] = Whh1[off];
    }
    if (tid < 8) sb[tid] = bih1[j0 + tid] + bhh1[j0 + tid];

    // zero initial state in ALL buffers (each CTA its 64-float slice)
    if (tid < 64) {
        int o = blockIdx.x * 64 + tid;
        __stcg(&g_h0buf[0][o], 0.f); __stcg(&g_h0buf[1][o], 0.f);
        __stcg(&g_h1buf[0][o], 0.f); __stcg(&g_h1buf[1][o], 0.f);
    }
    grid_barrier();

    for (int s = 0; s <= SEQ; s++) {
        // prefetch a0 term for layer-0
        float a0v = 0.f;
        if (tid < 64 && s < SEQ) {
            int b = tid >> 3, jj = tid & 7;
            a0v = __ldcg(&g_a0[((size_t)s * 8 + b) * H_SZ + j0 + jj]);
        }

        // load H0(s) [buf s&1] and H1(s-1) [buf (s+1)&1] once into smem
        {
            const float4* s0 = (const float4*)g_h0buf[s & 1];
            const float4* s1 = (const float4*)g_h1buf[(s + 1) & 1];
            float4* d0 = (float4*)sh0;
            float4* d1 = (float4*)sh1;
#pragma unroll
            for (int i = 0; i < 8; i++) {
                d0[tid + i * 256] = __ldcg(s0 + tid + i * 256);
                d1[tid + i * 256] = __ldcg(s1 + tid + i * 256);
            }
        }
        __syncthreads();

        // packed f32x2 inner loop: c0 = layer0 acc, c1 = layer1 acc
        unsigned long long c0[4] = {0ull, 0ull, 0ull, 0ull};
        unsigned long long c1[4] = {0ull, 0ull, 0ull, 0ull};
#pragma unroll
        for (int i = 0; i < 32; i++) {
            const int k = kg + (i << 5);
            unsigned long long W0 = pack2(W0r[i]);
            unsigned long long W1 = pack2(W1r[i]);
            unsigned long long W2 = pack2(W2r[i]);
            const ulonglong2* hp = (const ulonglong2*)(sh0 + k * 8);
            const ulonglong2* hq = (const ulonglong2*)(sh1 + k * 8);
            ulonglong2 p0 = hp[0], p1 = hp[1];
            ulonglong2 q0 = hq[0], q1 = hq[1];
            c0[0] = fma2(W0, p0.x, c0[0]); c0[1] = fma2(W0, p0.y, c0[1]);
            c0[2] = fma2(W0, p1.x, c0[2]); c0[3] = fma2(W0, p1.y, c0[3]);
            c1[0] = fma2(W1, p0.x, c1[0]); c1[1] = fma2(W1, p0.y, c1[1]);
            c1[2] = fma2(W1, p1.x, c1[2]); c1[3] = fma2(W1, p1.y, c1[3]);
            c1[0] = fma2(W2, q0.x, c1[0]); c1[1] = fma2(W2, q0.y, c1[1]);
            c1[2] = fma2(W2, q1.x, c1[2]); c1[3] = fma2(W2, q1.y, c1[3]);
        }
        float a0[8], a1[8];
#pragma unroll
        for (int q = 0; q < 4; q++) {
            unpack2(c0[q], a0[q * 2], a0[q * 2 + 1]);
            unpack2(c1[q], a1[q * 2], a1[q * 2 + 1]);
        }
#pragma unroll
        for (int q = 0; q < 8; q++) {
            a0[q] += __shfl_xor_sync(0xffffffffu, a0[q], 8);
            a0[q] += __shfl_xor_sync(0xffffffffu, a0[q], 16);
            a1[q] += __shfl_xor_sync(0xffffffffu, a1[q], 8);
            a1[q] += __shfl_xor_sync(0xffffffffu, a1[q], 16);
        }
        if (lane < 8) {   // lane == jl here
#pragma unroll
            for (int b = 0; b < 8; b++) {
                sred[warp * 64 + lane * 8 + b]       = a0[b];
                sred[512 + warp * 64 + lane * 8 + b] = a1[b];
            }
        }
        __syncthreads();

        if (tid < 128) {
            const int set = tid >> 6;
            const int o   = tid & 63;
            const int b   = o >> 3, jj = o & 7;
            float v = 0.f;
#pragma unroll
            for (int w = 0; w < 8; w++) v += sred[set * 512 + w * 64 + jj * 8 + b];
            if (set == 0) {
                if (s < SEQ) {
                    float h = tanhf(v + a0v);
                    __stcg(&g_h0buf[(s + 1) & 1][(j0 + jj) * 8 + b], h);
                }
            } else {
                if (s >= 1) {
                    float h = tanhf(v + sb[jj]);
                    __stcg(&g_h1buf[s & 1][(j0 + jj) * 8 + b], h);
                    g_outs[((size_t)b * SEQ + (s - 1)) * H_SZ + j0 + jj] = f2tf32(h);
                }
            }
        }
        if (s < SEQ) grid_barrier();
    }
}

// ---------------------------------------------------------------------------
// Kernel 3: output projection  logits = g_outs @ g_wout + b_out
//   M=4096, N=32000, K=1024. 256x128x32 tiles, 64x64 warp tiles,
//   tf32 mma m16n8k8, 3-stage cp.async pipeline (PROVEN round-2 version).
// ---------------------------------------------------------------------------
#define TM 256
#define TN 128
#define TK 32
#define SA_STRIDE 36
#define SB_STRIDE 132
#define SA_FLOATS (TM * SA_STRIDE)   // 9216
#define SB_FLOATS (TK * SB_STRIDE)   // 4224
#define NSTAGE 3
#define GEMM_SMEM_BYTES (NSTAGE * (SA_FLOATS + SB_FLOATS) * 4)  // 161280

__device__ __forceinline__ void gemm_stage(
    int kt, float* sA, float* sB, int m0, int n0, int tid)
{
    const int k0 = kt * TK;
    const int ar = tid >> 3, ac = (tid & 7) * 4;
#pragma unroll
    for (int i = 0; i < 8; i++)
        cp16(sA + (ar + i * 32) * SA_STRIDE + ac,
             g_outs + (size_t)(m0 + ar + i * 32) * H_SZ + k0 + ac);
    const int br = tid >> 5, bc = (tid & 31) * 4;
#pragma unroll
    for (int i = 0; i < 4; i++)
        cp16(sB + (br + i * 8) * SB_STRIDE + bc,
             g_wout + (size_t)(k0 + br + i * 8) * V_SZ + n0 + bc);
}

__global__ void __launch_bounds__(256, 1) k_out_gemm(
    const float* __restrict__ bout, float* __restrict__ out)
{
    extern __shared__ float sm3[];
    float* sA = sm3;                          // NSTAGE x 9216
    float* sB = sm3 + NSTAGE * SA_FLOATS;     // NSTAGE x 4224

    const int tid  = threadIdx.x;
    const int m0   = blockIdx.x * TM;   // m-fast: B tiles reused via L2
    const int n0   = blockIdx.y * TN;
    const int warp = tid >> 5;
    const int lane = tid & 31;
    const int g    = lane >> 2;
    const int tg   = lane & 3;
    const int wm   = warp & 3;   // 4 warps along M (64 rows each)
    const int wn   = warp >> 2;  // 2 warps along N (64 cols each)

    float acc[4][8][4];
#pragma unroll
    for (int mt = 0; mt < 4; mt++)
#pragma unroll
        for (int nt = 0; nt < 8; nt++)
#pragma unroll
            for (int q = 0; q < 4; q++) acc[mt][nt][q] = 0.f;

    // prologue: stages 0 and 1
    gemm_stage(0, sA, sB, m0, n0, tid);
    CP_COMMIT();
    gemm_stage(1, sA + SA_FLOATS, sB + SB_FLOATS, m0, n0, tid);
    CP_COMMIT();

    for (int kt = 0; kt < 32; kt++) {
        // issue stage kt+2 (buffer freed by the __syncthreads at end of kt-1)
        if (kt + 2 < 32) {
            int st = (kt + 2) % NSTAGE;
            gemm_stage(kt + 2, sA + st * SA_FLOATS, sB + st * SB_FLOATS, m0, n0, tid);
        }
        CP_COMMIT();
        CP_WAIT2();          // all but the 2 newest groups done -> stage kt ready
        __syncthreads();

        const float* A = sA + (kt % NSTAGE) * SA_FLOATS;
        const float* B = sB + (kt % NSTAGE) * SB_FLOATS;
#pragma unroll
        for (int kk = 0; kk < 4; kk++) {
            const int k8 = kk * 8;
            uint32_t af[4][4];
#pragma unroll
            for (int mt = 0; mt < 4; mt++) {
                int r = wm * 64 + mt * 16 + g;
                af[mt][0] = __float_as_uint(A[r * SA_STRIDE + k8 + tg]);
                af[mt][1] = __float_as_uint(A[(r + 8) * SA_STRIDE + k8 + tg]);
                af[mt][2] = __float_as_uint(A[r * SA_STRIDE + k8 + tg + 4]);
                af[mt][3] = __float_as_uint(A[(r + 8) * SA_STRIDE + k8 + tg + 4]);
            }
            uint32_t bf[8][2];
#pragma unroll
            for (int nt = 0; nt < 8; nt++) {
                int c = wn * 64 + nt * 8 + g;
                bf[nt][0] = __float_as_uint(B[(k8 + tg) * SB_STRIDE + c]);
                bf[nt][1] = __float_as_uint(B[(k8 + tg + 4) * SB_STRIDE + c]);
            }
#pragma unroll
            for (int mt = 0; mt < 4; mt++)
#pragma unroll
                for (int nt = 0; nt < 8; nt++) {
                    asm volatile(
                        "mma.sync.aligned.m16n8k8.row.col.f32.tf32.tf32.f32 "
                        "{%0,%1,%2,%3},{%4,%5,%6,%7},{%8,%9},{%0,%1,%2,%3};\n"
                        : "+f"(acc[mt][nt][0]), "+f"(acc[mt][nt][1]),
                          "+f"(acc[mt][nt][2]), "+f"(acc[mt][nt][3])
                        : "r"(af[mt][0]), "r"(af[mt][1]), "r"(af[mt][2]), "r"(af[mt][3]),
                          "r"(bf[nt][0]), "r"(bf[nt][1]));
                }
        }
        __syncthreads();   // all warps done with stage kt before it is re-filled
    }

    // epilogue: bias + store
#pragma unroll
    for (int nt = 0; nt < 8; nt++) {
        int c = n0 + wn * 64 + nt * 8 + 2 * tg;
        float b0 = bout[c], b1 = bout[c + 1];
#pragma unroll
        for (int mt = 0; mt < 4; mt++) {
            int r = m0 + wm * 64 + mt * 16 + g;
            float2 v0 = make_float2(acc[mt][nt][0] + b0, acc[mt][nt][1] + b1);
            float2 v1 = make_float2(acc[mt][nt][2] + b0, acc[mt][nt][3] + b1);
            *(float2*)(out + (size_t)r * V_SZ + c) = v0;
            *(float2*)(out + (size_t)(r + 8) * V_SZ + c) = v1;
        }
    }
}

// ---------------------------------------------------------------------------
// Kernel 4: final hidden states h0, h1 (both end in buffer 0 after 512 steps)
// ---------------------------------------------------------------------------
__global__ void __launch_bounds__(256) k_tail(float* __restrict__ out)
{
    int idx = blockIdx.x * 256 + threadIdx.x;
    if (idx < BATCH * H_SZ) {
        int b = idx >> 10, j = idx & 1023;
        out[LOGITS + idx]                = g_h0buf[0][j * 8 + b];
        out[LOGITS + BATCH * H_SZ + idx] = g_h1buf[0][j * 8 + b];
    }
}

// ---------------------------------------------------------------------------
// Launch
// ---------------------------------------------------------------------------
extern "C" void kernel_launch(void* const* d_in, const int* in_sizes, int n_in,
                              void* d_out, int out_size)
{
    const int*   x     = (const int*)  d_in[0];
    const float* emb   = (const float*)d_in[1];
    const float* W_ih0 = (const float*)d_in[2];
    const float* b_ih0 = (const float*)d_in[3];
    const float* W_hh0 = (const float*)d_in[4];
    const float* b_hh0 = (const float*)d_in[5];
    const float* W_ih1 = (const float*)d_in[6];
    const float* b_ih1 = (const float*)d_in[7];
    const float* W_hh1 = (const float*)d_in[8];
    const float* b_hh1 = (const float*)d_in[9];
    const float* W_out = (const float*)d_in[10];
    const float* b_out = (const float*)d_in[11];
    float* out = (float*)d_out;

    cudaFuncSetAttribute(k_rnn, cudaFuncAttributeMaxDynamicSharedMemorySize,
                         RNN_SMEM_BYTES);
    cudaFuncSetAttribute(k_out_gemm, cudaFuncAttributeMaxDynamicSharedMemorySize,
                         GEMM_SMEM_BYTES);

    // 0) tf32 pre-round of W_out
    k_cvt<<<32000, 256>>>(W_out);

    // 1) input-term GEMM
    k_embed_gemm<<<dim3(16, 64), 256>>>(x, emb, W_ih0, b_ih0, b_hh0);

    // 2) pipelined persistent recurrence (128 co-resident CTAs)
    k_rnn<<<NCTA, 256, RNN_SMEM_BYTES>>>(W_hh0, W_ih1, W_hh1, b_ih1, b_hh1);

    // 3) output projection, m-fast rasterization: grid (m=16, n=250)
    k_out_gemm<<<dim3(16, 250), 256, GEMM_SMEM_BYTES>>>(b_out, out);

    // 4) final hidden states
    k_tail<<<32, 256>>>(out);
}

// round 5
// speedup vs baseline: 1.6709x; 1.0183x over previous
#include <cuda_runtime.h>
#include <cuda_bf16.h>
#include <cstdint>
#include <cstddef>

// ---------------------------------------------------------------------------
// Problem constants
// ---------------------------------------------------------------------------
#define V_SZ   32000
#define E_DIM  256
#define H_SZ   1024
#define BATCH  8
#define SEQ    512
#define ROWS   (BATCH*SEQ)          // 4096
#define LOGITS ((size_t)ROWS*V_SZ)  // 131072000

// ---------------------------------------------------------------------------
// Device scratch (static allocation — no cudaMalloc allowed)
// ---------------------------------------------------------------------------
__device__ float g_a0[(size_t)ROWS * H_SZ];     // input term [t*8+b][h]
__device__ float g_outs[(size_t)ROWS * H_SZ];   // h1 per step (tf32-rounded), row r=b*512+t
__device__ float g_wout[(size_t)H_SZ * V_SZ];   // tf32-rounded copy of W_out
__device__ float g_h0buf[2][H_SZ * BATCH];      // [j*8+b] layout
__device__ float g_h1buf[2][H_SZ * BATCH];
__device__ unsigned          g_barc = 0;
__device__ volatile unsigned g_barg = 0;

// ---------------------------------------------------------------------------
// Small helpers
// ---------------------------------------------------------------------------
__device__ __forceinline__ float f2tf32(float x)
{
    uint32_t u;
    asm("cvt.rna.tf32.f32 %0, %1;" : "=r"(u) : "f"(x));
    return __uint_as_float(u);
}
__device__ __forceinline__ float4 cvt4(float4 v)
{
    v.x = f2tf32(v.x); v.y = f2tf32(v.y); v.z = f2tf32(v.z); v.w = f2tf32(v.w);
    return v;
}
__device__ __forceinline__ unsigned long long fma2(
    unsigned long long a, unsigned long long b, unsigned long long c)
{
    unsigned long long d;
    asm("fma.rn.f32x2 %0, %1, %2, %3;" : "=l"(d) : "l"(a), "l"(b), "l"(c));
    return d;
}
__device__ __forceinline__ unsigned long long pack2(float w)
{
    unsigned long long d;
    asm("mov.b64 %0, {%1, %1};" : "=l"(d) : "r"(__float_as_uint(w)));
    return d;
}
__device__ __forceinline__ void unpack2(unsigned long long v, float& lo, float& hi)
{
    uint32_t l, h;
    asm("mov.b64 {%0, %1}, %2;" : "=r"(l), "=r"(h) : "l"(v));
    lo = __uint_as_float(l); hi = __uint_as_float(h);
}
__device__ __forceinline__ void cp16(float* s, const float* g)
{
    unsigned sa = (unsigned)__cvta_generic_to_shared(s);
    asm volatile("cp.async.cg.shared.global [%0], [%1], 16;" :: "r"(sa), "l"(g));
}
#define CP_COMMIT() asm volatile("cp.async.commit_group;")
#define CP_WAIT2()  asm volatile("cp.async.wait_group 2;")

// ---------------------------------------------------------------------------
// Kernel 0: pre-round W_out to tf32 (rna) into g_wout
// ---------------------------------------------------------------------------
__global__ void __launch_bounds__(256) k_cvt(const float* __restrict__ W)
{
    size_t i = ((size_t)blockIdx.x * 256 + threadIdx.x) * 4;
    float4 v = *(const float4*)(W + i);
    *(float4*)(g_wout + i) = cvt4(v);
}

// ---------------------------------------------------------------------------
// Kernel 1: embedding gather + input GEMM
// ---------------------------------------------------------------------------
__global__ void __launch_bounds__(256) k_embed_gemm(
    const int* __restrict__ x, const float* __restrict__ emb,
    const float* __restrict__ Wih0, const float* __restrict__ bih0,
    const float* __restrict__ bhh0)
{
    __shared__ float sA[64][68];
    __shared__ float sB[64][68];
    const int n0 = blockIdx.x * 64;
    const int m0 = blockIdx.y * 64;
    const int tid = threadIdx.x;
    const int ty = tid >> 4, tx = tid & 15;

    float acc[4][4];
#pragma unroll
    for (int i = 0; i < 4; i++)
#pragma unroll
        for (int j = 0; j < 4; j++) acc[i][j] = 0.f;

    for (int k0 = 0; k0 < E_DIM; k0 += 64) {
#pragma unroll
        for (int i = 0; i < 4; i++) {
            int r  = (tid >> 4) + i * 16;
            int c4 = tid & 15;
            int rg = m0 + r;
            int t  = rg >> 3, b = rg & 7;
            int tok = x[b * SEQ + t];
            float4 v = *(const float4*)(emb + (size_t)tok * E_DIM + k0 + c4 * 4);
            *(float4*)&sA[r][c4 * 4] = v;
        }
#pragma unroll
        for (int i = 0; i < 4; i++) {
            int kr = (tid >> 4) + i * 16;
            int c4 = tid & 15;
            float4 v = *(const float4*)(Wih0 + (size_t)(k0 + kr) * H_SZ + n0 + c4 * 4);
            *(float4*)&sB[kr][c4 * 4] = v;
        }
        __syncthreads();
#pragma unroll 8
        for (int k = 0; k < 64; k++) {
            float a[4], bb[4];
#pragma unroll
            for (int i = 0; i < 4; i++) a[i] = sA[ty * 4 + i][k];
#pragma unroll
            for (int j = 0; j < 4; j++) bb[j] = sB[k][tx * 4 + j];
#pragma unroll
            for (int i = 0; i < 4; i++)
#pragma unroll
                for (int j = 0; j < 4; j++) acc[i][j] += a[i] * bb[j];
        }
        __syncthreads();
    }
#pragma unroll
    for (int i = 0; i < 4; i++) {
        int r = m0 + ty * 4 + i;
#pragma unroll
        for (int j = 0; j < 4; j++) {
            int n = n0 + tx * 4 + j;
            g_a0[(size_t)r * H_SZ + n] = acc[i][j] + bih0[n] + bhh0[n];
        }
    }
}

// ---------------------------------------------------------------------------
// Kernel 2: persistent pipelined recurrence.
//   Superstep s (0..512): H0(s+1)=tanh(a0[s]+H0(s)W0)  [s<512]
//                         H1(s)  =tanh(H0(s)W1+H1(s-1)W2+b) [s>=1]
//   Weights in REGISTERS. h-vectors streamed in 8 chunks via cp.async,
//   overlapped with the FMA loop. Central atomic grid barrier (proven).
// ---------------------------------------------------------------------------
#define NCTA 128

__device__ __forceinline__ void grid_barrier()
{
    __syncthreads();
    __threadfence();
    if (threadIdx.x == 0) {
        unsigned gen = g_barg;
        unsigned a = atomicAdd(&g_barc, 1u);
        if (a == NCTA - 1) {
            g_barc = 0;
            __threadfence();
            g_barg = gen + 1;
        } else {
            while (g_barg == gen) { }
        }
    }
    __syncthreads();
}

// stage chunk c: floats [1024c, 1024c+1024) of both h vectors into smem
__device__ __forceinline__ void rnn_stage(
    int c, float* sh0, float* sh1,
    const float* h0g, const float* h1g, int tid)
{
    const int off = c * 1024 + tid * 4;
    cp16(sh0 + off, h0g + off);
    cp16(sh1 + off, h1g + off);
}

// SMEM (floats): sh0[8192] sh1[8192] sred[1024] sb[8] = 17416 floats = 69,664 B
#define RNN_SMEM_FLOATS 17416
#define RNN_SMEM_BYTES  (RNN_SMEM_FLOATS * 4)

__global__ void __launch_bounds__(256, 1) k_rnn(
    const float* __restrict__ Whh0, const float* __restrict__ Wih1,
    const float* __restrict__ Whh1, const float* __restrict__ bih1,
    const float* __restrict__ bhh1)
{
    extern __shared__ float sm[];
    float* sh0  = sm;
    float* sh1  = sm + 8192;
    float* sred = sm + 16384;   // 1024 (two sets of 512)
    float* sb   = sm + 17408;   // 8

    const int tid  = threadIdx.x;
    const int j0   = blockIdx.x * 8;
    const int jl   = tid & 7;
    const int kg   = tid >> 3;       // 0..31
    const int lane = tid & 31;
    const int warp = tid >> 5;

    // weight slices into REGISTERS: Wr[i] = W[kg+32i][j0+jl]
    float W0r[32], W1r[32], W2r[32];
#pragma unroll
    for (int i = 0; i < 32; i++) {
        size_t off = (size_t)(kg + 32 * i) * H_SZ + j0 + jl;
        W0r[i] = Whh0[off];
        W1r[i] = Wih1[off];
        W2r[i] = Whh1[off];
    }
    if (tid < 8) sb[tid] = bih1[j0 + tid] + bhh1[j0 + tid];

    // zero initial state in ALL buffers (each CTA its 64-float slice)
    if (tid < 64) {
        int o = blockIdx.x * 64 + tid;
        __stcg(&g_h0buf[0][o], 0.f); __stcg(&g_h0buf[1][o], 0.f);
        __stcg(&g_h1buf[0][o], 0.f); __stcg(&g_h1buf[1][o], 0.f);
    }
    grid_barrier();

    for (int s = 0; s <= SEQ; s++) {
        const float* h0g = g_h0buf[s & 1];
        const float* h1g = g_h1buf[(s + 1) & 1];

        // start streaming h chunks 0,1 immediately
        rnn_stage(0, sh0, sh1, h0g, h1g, tid); CP_COMMIT();
        rnn_stage(1, sh0, sh1, h0g, h1g, tid); CP_COMMIT();

        // prefetch a0 term for layer-0 (overlaps with chunk pipeline)
        float a0v = 0.f;
        if (tid < 64 && s < SEQ) {
            int b = tid >> 3, jj = tid & 7;
            a0v = __ldcg(&g_a0[((size_t)s * 8 + b) * H_SZ + j0 + jj]);
        }

        // chunked compute: chunk c consumes k in [128c, 128c+128)
        unsigned long long c0[4] = {0ull, 0ull, 0ull, 0ull};
        unsigned long long c1[4] = {0ull, 0ull, 0ull, 0ull};
#pragma unroll
        for (int c = 0; c < 8; c++) {
            if (c + 2 < 8) rnn_stage(c + 2, sh0, sh1, h0g, h1g, tid);
            CP_COMMIT();          // unconditional: keeps group count stable
            CP_WAIT2();           // chunk c resident (c+1, c+2 in flight)
            __syncthreads();      // cross-thread visibility of cp.async data
#pragma unroll
            for (int ii = 0; ii < 4; ii++) {
                const int i = c * 4 + ii;
                const int k = kg + (i << 5);
                unsigned long long W0 = pack2(W0r[i]);
                unsigned long long W1 = pack2(W1r[i]);
                unsigned long long W2 = pack2(W2r[i]);
                const ulonglong2* hp = (const ulonglong2*)(sh0 + k * 8);
                const ulonglong2* hq = (const ulonglong2*)(sh1 + k * 8);
                ulonglong2 p0 = hp[0], p1 = hp[1];
                ulonglong2 q0 = hq[0], q1 = hq[1];
                c0[0] = fma2(W0, p0.x, c0[0]); c0[1] = fma2(W0, p0.y, c0[1]);
                c0[2] = fma2(W0, p1.x, c0[2]); c0[3] = fma2(W0, p1.y, c0[3]);
                c1[0] = fma2(W1, p0.x, c1[0]); c1[1] = fma2(W1, p0.y, c1[1]);
                c1[2] = fma2(W1, p1.x, c1[2]); c1[3] = fma2(W1, p1.y, c1[3]);
                c1[0] = fma2(W2, q0.x, c1[0]); c1[1] = fma2(W2, q0.y, c1[1]);
                c1[2] = fma2(W2, q1.x, c1[2]); c1[3] = fma2(W2, q1.y, c1[3]);
            }
        }
        float a0[8], a1[8];
#pragma unroll
        for (int q = 0; q < 4; q++) {
            unpack2(c0[q], a0[q * 2], a0[q * 2 + 1]);
            unpack2(c1[q], a1[q * 2], a1[q * 2 + 1]);
        }
#pragma unroll
        for (int q = 0; q < 8; q++) {
            a0[q] += __shfl_xor_sync(0xffffffffu, a0[q], 8);
            a0[q] += __shfl_xor_sync(0xffffffffu, a0[q], 16);
            a1[q] += __shfl_xor_sync(0xffffffffu, a1[q], 8);
            a1[q] += __shfl_xor_sync(0xffffffffu, a1[q], 16);
        }
        if (lane < 8) {   // lane == jl here
#pragma unroll
            for (int b = 0; b < 8; b++) {
                sred[warp * 64 + lane * 8 + b]       = a0[b];
                sred[512 + warp * 64 + lane * 8 + b] = a1[b];
            }
        }
        __syncthreads();

        if (tid < 128) {
            const int set = tid >> 6;
            const int o   = tid & 63;
            const int b   = o >> 3, jj = o & 7;
            float v = 0.f;
#pragma unroll
            for (int w = 0; w < 8; w++) v += sred[set * 512 + w * 64 + jj * 8 + b];
            if (set == 0) {
                if (s < SEQ) {
                    float h = tanhf(v + a0v);
                    __stcg(&g_h0buf[(s + 1) & 1][(j0 + jj) * 8 + b], h);
                }
            } else {
                if (s >= 1) {
                    float h = tanhf(v + sb[jj]);
                    __stcg(&g_h1buf[s & 1][(j0 + jj) * 8 + b], h);
                    g_outs[((size_t)b * SEQ + (s - 1)) * H_SZ + j0 + jj] = f2tf32(h);
                }
            }
        }
        if (s < SEQ) grid_barrier();
    }
}

// ---------------------------------------------------------------------------
// Kernel 3: output projection  logits = g_outs @ g_wout + b_out
//   M=4096, N=32000, K=1024. 256x128x32 tiles, 64x64 warp tiles,
//   tf32 mma m16n8k8, 3-stage cp.async pipeline (PROVEN round-2 version).
// ---------------------------------------------------------------------------
#define TM 256
#define TN 128
#define TK 32
#define SA_STRIDE 36
#define SB_STRIDE 132
#define SA_FLOATS (TM * SA_STRIDE)   // 9216
#define SB_FLOATS (TK * SB_STRIDE)   // 4224
#define NSTAGE 3
#define GEMM_SMEM_BYTES (NSTAGE * (SA_FLOATS + SB_FLOATS) * 4)  // 161280

__device__ __forceinline__ void gemm_stage(
    int kt, float* sA, float* sB, int m0, int n0, int tid)
{
    const int k0 = kt * TK;
    const int ar = tid >> 3, ac = (tid & 7) * 4;
#pragma unroll
    for (int i = 0; i < 8; i++)
        cp16(sA + (ar + i * 32) * SA_STRIDE + ac,
             g_outs + (size_t)(m0 + ar + i * 32) * H_SZ + k0 + ac);
    const int br = tid >> 5, bc = (tid & 31) * 4;
#pragma unroll
    for (int i = 0; i < 4; i++)
        cp16(sB + (br + i * 8) * SB_STRIDE + bc,
             g_wout + (size_t)(k0 + br + i * 8) * V_SZ + n0 + bc);
}

__global__ void __launch_bounds__(256, 1) k_out_gemm(
    const float* __restrict__ bout, float* __restrict__ out)
{
    extern __shared__ float sm3[];
    float* sA = sm3;                          // NSTAGE x 9216
    float* sB = sm3 + NSTAGE * SA_FLOATS;     // NSTAGE x 4224

    const int tid  = threadIdx.x;
    const int m0   = blockIdx.x * TM;   // m-fast: B tiles reused via L2
    const int n0   = blockIdx.y * TN;
    const int warp = tid >> 5;
    const int lane = tid & 31;
    const int g    = lane >> 2;
    const int tg   = lane & 3;
    const int wm   = warp & 3;   // 4 warps along M (64 rows each)
    const int wn   = warp >> 2;  // 2 warps along N (64 cols each)

    float acc[4][8][4];
#pragma unroll
    for (int mt = 0; mt < 4; mt++)
#pragma unroll
        for (int nt = 0; nt < 8; nt++)
#pragma unroll
            for (int q = 0; q < 4; q++) acc[mt][nt][q] = 0.f;

    // prologue: stages 0 and 1
    gemm_stage(0, sA, sB, m0, n0, tid);
    CP_COMMIT();
    gemm_stage(1, sA + SA_FLOATS, sB + SB_FLOATS, m0, n0, tid);
    CP_COMMIT();

    for (int kt = 0; kt < 32; kt++) {
        // issue stage kt+2 (buffer freed by the __syncthreads at end of kt-1)
        if (kt + 2 < 32) {
            int st = (kt + 2) % NSTAGE;
            gemm_stage(kt + 2, sA + st * SA_FLOATS, sB + st * SB_FLOATS, m0, n0, tid);
        }
        CP_COMMIT();
        CP_WAIT2();          // all but the 2 newest groups done -> stage kt ready
        __syncthreads();

        const float* A = sA + (kt % NSTAGE) * SA_FLOATS;
        const float* B = sB + (kt % NSTAGE) * SB_FLOATS;
#pragma unroll
        for (int kk = 0; kk < 4; kk++) {
            const int k8 = kk * 8;
            uint32_t af[4][4];
#pragma unroll
            for (int mt = 0; mt < 4; mt++) {
                int r = wm * 64 + mt * 16 + g;
                af[mt][0] = __float_as_uint(A[r * SA_STRIDE + k8 + tg]);
                af[mt][1] = __float_as_uint(A[(r + 8) * SA_STRIDE + k8 + tg]);
                af[mt][2] = __float_as_uint(A[r * SA_STRIDE + k8 + tg + 4]);
                af[mt][3] = __float_as_uint(A[(r + 8) * SA_STRIDE + k8 + tg + 4]);
            }
            uint32_t bf[8][2];
#pragma unroll
            for (int nt = 0; nt < 8; nt++) {
                int c = wn * 64 + nt * 8 + g;
                bf[nt][0] = __float_as_uint(B[(k8 + tg) * SB_STRIDE + c]);
                bf[nt][1] = __float_as_uint(B[(k8 + tg + 4) * SB_STRIDE + c]);
            }
#pragma unroll
            for (int mt = 0; mt < 4; mt++)
#pragma unroll
                for (int nt = 0; nt < 8; nt++) {
                    asm volatile(
                        "mma.sync.aligned.m16n8k8.row.col.f32.tf32.tf32.f32 "
                        "{%0,%1,%2,%3},{%4,%5,%6,%7},{%8,%9},{%0,%1,%2,%3};\n"
                        : "+f"(acc[mt][nt][0]), "+f"(acc[mt][nt][1]),
                          "+f"(acc[mt][nt][2]), "+f"(acc[mt][nt][3])
                        : "r"(af[mt][0]), "r"(af[mt][1]), "r"(af[mt][2]), "r"(af[mt][3]),
                          "r"(bf[nt][0]), "r"(bf[nt][1]));
                }
        }
        __syncthreads();   // all warps done with stage kt before it is re-filled
    }

    // epilogue: bias + store
#pragma unroll
    for (int nt = 0; nt < 8; nt++) {
        int c = n0 + wn * 64 + nt * 8 + 2 * tg;
        float b0 = bout[c], b1 = bout[c + 1];
#pragma unroll
        for (int mt = 0; mt < 4; mt++) {
            int r = m0 + wm * 64 + mt * 16 + g;
            float2 v0 = make_float2(acc[mt][nt][0] + b0, acc[mt][nt][1] + b1);
            float2 v1 = make_float2(acc[mt][nt][2] + b0, acc[mt][nt][3] + b1);
            *(float2*)(out + (size_t)r * V_SZ + c) = v0;
            *(float2*)(out + (size_t)(r + 8) * V_SZ + c) = v1;
        }
    }
}

// ---------------------------------------------------------------------------
// Kernel 4: final hidden states h0, h1 (both end in buffer 0 after 512 steps)
// ---------------------------------------------------------------------------
__global__ void __launch_bounds__(256) k_tail(float* __restrict__ out)
{
    int idx = blockIdx.x * 256 + threadIdx.x;
    if (idx < BATCH * H_SZ) {
        int b = idx >> 10, j = idx & 1023;
        out[LOGITS + idx]                = g_h0buf[0][j * 8 + b];
        out[LOGITS + BATCH * H_SZ + idx] = g_h1buf[0][j * 8 + b];
    }
}

// ---------------------------------------------------------------------------
// Launch
// ---------------------------------------------------------------------------
extern "C" void kernel_launch(void* const* d_in, const int* in_sizes, int n_in,
                              void* d_out, int out_size)
{
    const int*   x     = (const int*)  d_in[0];
    const float* emb   = (const float*)d_in[1];
    const float* W_ih0 = (const float*)d_in[2];
    const float* b_ih0 = (const float*)d_in[3];
    const float* W_hh0 = (const float*)d_in[4];
    const float* b_hh0 = (const float*)d_in[5];
    const float* W_ih1 = (const float*)d_in[6];
    const float* b_ih1 = (const float*)d_in[7];
    const float* W_hh1 = (const float*)d_in[8];
    const float* b_hh1 = (const float*)d_in[9];
    const float* W_out = (const float*)d_in[10];
    const float* b_out = (const float*)d_in[11];
    float* out = (float*)d_out;

    cudaFuncSetAttribute(k_rnn, cudaFuncAttributeMaxDynamicSharedMemorySize,
                         RNN_SMEM_BYTES);
    cudaFuncSetAttribute(k_out_gemm, cudaFuncAttributeMaxDynamicSharedMemorySize,
                         GEMM_SMEM_BYTES);

    // 0) tf32 pre-round of W_out
    k_cvt<<<32000, 256>>>(W_out);

    // 1) input-term GEMM
    k_embed_gemm<<<dim3(16, 64), 256>>>(x, emb, W_ih0, b_ih0, b_hh0);

    // 2) pipelined persistent recurrence (128 co-resident CTAs)
    k_rnn<<<NCTA, 256, RNN_SMEM_BYTES>>>(W_hh0, W_ih1, W_hh1, b_ih1, b_hh1);

    // 3) output projection, m-fast rasterization: grid (m=16, n=250)
    k_out_gemm<<<dim3(16, 250), 256, GEMM_SMEM_BYTES>>>(b_out, out);

    // 4) final hidden states
    k_tail<<<32, 256>>>(out);
}